// round 1
// baseline (speedup 1.0000x reference)
#include <cuda_runtime.h>
#include <cstdint>

// ---------------------------------------------------------------------------
// SparseResUQueryNet: history sparse conv (1->32) + time max-pool + query
// sparse conv (32->32) evaluated per point.
//
// Keys pack into 28 bits: ((t*256+x)*256+y)*256+z  (t<16, coords in [1,250]).
// Neighbor offsets dx,dy,dz in {-1,0,1} never carry across bytes.
// ---------------------------------------------------------------------------

#define H1_LOG 22
#define H2_LOG 21
#define H1_SIZE (1u << H1_LOG)
#define H2_SIZE (1u << H2_LOG)
#define H1_MASK (H1_SIZE - 1u)
#define H2_MASK (H2_SIZE - 1u)
#define EMPTY_KEY 0xFFFFFFFFu
#define FULL_MASK 0xFFFFFFFFu

// Static scratch (no cudaMalloc allowed).
__device__ unsigned      g_h1_keys[H1_SIZE];                 // 16 MB
__device__ int           g_h1_vals[H1_SIZE];                 // 16 MB
__device__ unsigned      g_h2_keys[H2_SIZE];                 // 8 MB
__device__ unsigned char g_contested[H2_SIZE];               // 2 MB
__device__ unsigned      g_pooled[(size_t)H2_SIZE * 32];     // 256 MB (row = hash slot)

__device__ __forceinline__ unsigned hash1(unsigned k) {
    return (k * 2654435761u) >> (32 - H1_LOG);
}
__device__ __forceinline__ unsigned hash2(unsigned k) {
    return (k * 2654435761u) >> (32 - H2_LOG);
}
__device__ __forceinline__ unsigned deltaOf(int d) {
    int dx = d / 9 - 1, dy = (d / 3) % 3 - 1, dz = d % 3 - 1;
    return (unsigned)((dx << 16) + (dy << 8) + dz);
}
// Order-preserving float<->uint map (for atomicMax pooling).
__device__ __forceinline__ unsigned encf(float f) {
    unsigned b = __float_as_uint(f);
    return b ^ (unsigned)(((int)b >> 31) | 0x80000000);
}
__device__ __forceinline__ float decf(unsigned u) {
    unsigned x = ((int)u < 0) ? (u ^ 0x80000000u) : ~u;
    return __uint_as_float(x);
}

// ---------------------------------------------------------------------------
// K0: reset hash keys + contested flags (pooled is NOT reset: uncontested rows
// are fully overwritten, contested rows get zeroed in K1).
// ---------------------------------------------------------------------------
__global__ void k_reset() {
    unsigned i = blockIdx.x * blockDim.x + threadIdx.x;
    unsigned stride = gridDim.x * blockDim.x;
    for (unsigned s = i; s < H1_SIZE; s += stride) g_h1_keys[s] = EMPTY_KEY;
    for (unsigned s = i; s < H2_SIZE; s += stride) {
        g_h2_keys[s] = EMPTY_KEY;
        g_contested[s] = 0;
    }
}

// ---------------------------------------------------------------------------
// K1: insert history keys into H1 (value = voxel index) and pool keys into H2
// (row = slot). A thread that finds its pool key already present marks the
// slot contested and zeroes the pooled row (encoded 0 == minimal value).
// ---------------------------------------------------------------------------
__global__ void k_insert(const int4* __restrict__ hcoord,
                         const int* __restrict__ hbatch, int n) {
    int i = blockIdx.x * blockDim.x + threadIdx.x;
    if (i >= n) return;
    int4 c = hcoord[i];  // t, x, y, z
    unsigned key = ((unsigned)c.x << 24) | ((unsigned)c.y << 16) |
                   ((unsigned)c.z << 8) | (unsigned)c.w;
    unsigned s = hash1(key);
    while (true) {
        unsigned old = atomicCAS(&g_h1_keys[s], EMPTY_KEY, key);
        if (old == EMPTY_KEY || old == key) { g_h1_vals[s] = i; break; }
        s = (s + 1) & H1_MASK;
    }
    unsigned pk = ((unsigned)hbatch[i] << 24) | ((unsigned)c.y << 16) |
                  ((unsigned)c.z << 8) | (unsigned)c.w;
    s = hash2(pk);
    while (true) {
        unsigned old = atomicCAS(&g_h2_keys[s], EMPTY_KEY, pk);
        if (old == EMPTY_KEY) break;
        if (old == pk) {
            g_contested[s] = 1;
            unsigned* row = &g_pooled[(size_t)s * 32];
#pragma unroll
            for (int q = 0; q < 32; q++) row[q] = 0u;
            break;
        }
        s = (s + 1) & H2_MASK;
    }
}

// ---------------------------------------------------------------------------
// K2: one warp per history voxel. Compute bb[i][lane] = sum_d f_d * Wbb[d][lane]
// (27 neighbor lookups spread across lanes 0..26), then max-pool into the
// voxel's pool row: plain store if single-writer, else atomicMax on encoded.
// ---------------------------------------------------------------------------
__global__ void k_bb_pool(const float* __restrict__ hfeat,
                          const float* __restrict__ Wbb,
                          const int4* __restrict__ hcoord,
                          const int* __restrict__ hbatch, int n) {
    int w = (int)((blockIdx.x * blockDim.x + threadIdx.x) >> 5);
    int lane = threadIdx.x & 31;
    if (w >= n) return;
    int4 c = hcoord[w];
    unsigned key = ((unsigned)c.x << 24) | ((unsigned)c.y << 16) |
                   ((unsigned)c.z << 8) | (unsigned)c.w;
    float f = 0.0f;
    bool valid = false;
    if (lane < 27) {
        unsigned nk = key + deltaOf(lane);
        unsigned s = hash1(nk);
        while (true) {
            unsigned k2 = g_h1_keys[s];
            if (k2 == nk) { f = hfeat[g_h1_vals[s]]; valid = true; break; }
            if (k2 == EMPTY_KEY) break;
            s = (s + 1) & H1_MASK;
        }
    }
    unsigned m = __ballot_sync(FULL_MASK, valid);
    float acc = 0.0f;
    while (m) {  // ascending d == reference accumulation order
        int d = __ffs(m) - 1;
        m &= m - 1;
        float fd = __shfl_sync(FULL_MASK, f, d);
        acc = fmaf(fd, Wbb[d * 32 + lane], acc);
    }
    unsigned pk = ((unsigned)hbatch[w] << 24) | ((unsigned)c.y << 16) |
                  ((unsigned)c.z << 8) | (unsigned)c.w;
    unsigned s = hash2(pk);
    int slot = -1;
    while (true) {
        unsigned k2 = g_h2_keys[s];
        if (k2 == pk) { slot = (int)s; break; }
        if (k2 == EMPTY_KEY) break;  // cannot happen (inserted in K1)
        s = (s + 1) & H2_MASK;
    }
    if (slot >= 0) {
        unsigned e = encf(acc);
        unsigned* addr = &g_pooled[(size_t)slot * 32 + lane];
        if (g_contested[slot]) atomicMax(addr, e);
        else *addr = e;
    }
}

// ---------------------------------------------------------------------------
// K3: one warp per query point. Lanes 0..26 look up the 27 neighbor pool rows
// (~2% hit rate). For each valid delta: broadcast-load the pooled row into
// registers, decode once, and accumulate lane channel via 32 FFMAs against
// W_conv[d] (coalesced, L1-resident). Write [pt0..3 | 32 features].
// ---------------------------------------------------------------------------
__global__ void k_query(const float* __restrict__ points,
                        const float* __restrict__ Wc,
                        const int4* __restrict__ qcoord,
                        float* __restrict__ out, int npts) {
    int p = (int)((blockIdx.x * blockDim.x + threadIdx.x) >> 5);
    int lane = threadIdx.x & 31;
    if (p >= npts) return;
    int4 c = qcoord[p];  // b, x, y, z
    unsigned key = ((unsigned)c.x << 24) | ((unsigned)c.y << 16) |
                   ((unsigned)c.z << 8) | (unsigned)c.w;
    int r = -1;
    if (lane < 27) {
        unsigned nk = key + deltaOf(lane);
        unsigned s = hash2(nk);
        while (true) {
            unsigned k2 = g_h2_keys[s];
            if (k2 == nk) { r = (int)s; break; }
            if (k2 == EMPTY_KEY) break;
            s = (s + 1) & H2_MASK;
        }
    }
    unsigned m = __ballot_sync(FULL_MASK, r >= 0);
    float acc = 0.0f;
    while (m) {
        int d = __ffs(m) - 1;
        m &= m - 1;
        int rs = __shfl_sync(FULL_MASK, r, d);
        const uint4* prow = (const uint4*)&g_pooled[(size_t)rs * 32];
        float pv[32];
#pragma unroll
        for (int q = 0; q < 8; q++) {
            uint4 v = prow[q];  // uniform address -> broadcast
            pv[q * 4 + 0] = decf(v.x);
            pv[q * 4 + 1] = decf(v.y);
            pv[q * 4 + 2] = decf(v.z);
            pv[q * 4 + 3] = decf(v.w);
        }
        const float* wb = Wc + d * 1024 + lane;
#pragma unroll
        for (int k = 0; k < 32; k++) acc = fmaf(pv[k], wb[k * 32], acc);
    }
    float* o = out + (size_t)p * 36;
    o[4 + lane] = acc;
    if (lane < 4) o[lane] = points[(size_t)p * 5 + lane];
}

// ---------------------------------------------------------------------------
extern "C" void kernel_launch(void* const* d_in, const int* in_sizes, int n_in,
                              void* d_out, int out_size) {
    const float* hfeat  = (const float*)d_in[0];
    const float* points = (const float*)d_in[1];
    const float* Wbb    = (const float*)d_in[2];
    const float* Wc     = (const float*)d_in[3];
    const int4*  hcoord = (const int4*)d_in[4];
    const int*   hbatch = (const int*)d_in[5];
    const int4*  qcoord = (const int4*)d_in[6];
    float* out = (float*)d_out;

    int n    = in_sizes[5];      // history voxel count
    int npts = in_sizes[6] / 4;  // query point count

    const int TB = 256;
    k_reset<<<4096, TB>>>();
    k_insert<<<(n + TB - 1) / TB, TB>>>(hcoord, hbatch, n);
    {
        long long tw = (long long)n * 32;
        int blocks = (int)((tw + TB - 1) / TB);
        k_bb_pool<<<blocks, TB>>>(hfeat, Wbb, hcoord, hbatch, n);
    }
    {
        long long tw = (long long)npts * 32;
        int blocks = (int)((tw + TB - 1) / TB);
        k_query<<<blocks, TB>>>(points, Wc, qcoord, out, npts);
    }
}